// round 4
// baseline (speedup 1.0000x reference)
#include <cuda_runtime.h>
#include <cstdint>

#define NROWS  (1u << 20)
#define KTOP   1024
#define ECAP   4096
#define NEGF   (-1.0e9f)

// ---------------- scratch (module-load allocations, allowed) ----------------
__device__ float               g_score[NROWS];
__device__ float4              g_rec[NROWS * 2];     // [x1,y1,x2,y2][obj,conf,cls,0]
__device__ unsigned            g_hist1[65536];
__device__ unsigned            g_hist2[65536];
__device__ unsigned            g_cntA, g_cntE;
__device__ unsigned            g_b1, g_K2;
__device__ unsigned            g_Vk, g_teq;
__device__ uint2               g_A[KTOP];
__device__ unsigned            g_E[ECAP];
__device__ float4              g_boxes[KTOP];
__device__ float4              g_info[KTOP];
__device__ int                 g_valid[KTOP];
__device__ unsigned long long  g_M[KTOP * 16];

__device__ __forceinline__ unsigned fkey(float f) {
    unsigned u = __float_as_uint(f);
    return (u & 0x80000000u) ? ~u : (u | 0x80000000u);
}

// ---------------- K0: zero scratch ----------------
__global__ void k_init() {
    unsigned t = blockIdx.x * blockDim.x + threadIdx.x;
    if (t < 65536u) { g_hist1[t] = 0u; g_hist2[t] = 0u; }
    if (t == 0u) { g_cntA = 0u; g_cntE = 0u; }
}

// ---------------- K1: score + record + hist round 1 (warp per row) ----------------
__global__ void k_score(const float* __restrict__ pred) {
    unsigned gw   = (blockIdx.x * blockDim.x + threadIdx.x) >> 5;
    unsigned lane = threadIdx.x & 31u;
    if (gw >= NROWS) return;
    const float* row = pred + (size_t)gw * 85;

    float v0 = __ldg(row + lane);
    float v1 = __ldg(row + 32 + lane);
    float v2 = (lane < 21u) ? __ldg(row + 64 + lane) : -3.4e38f;

    float cx  = __shfl_sync(0xFFFFFFFFu, v0, 0);
    float cy  = __shfl_sync(0xFFFFFFFFu, v0, 1);
    float w   = __shfl_sync(0xFFFFFFFFu, v0, 2);
    float h   = __shfl_sync(0xFFFFFFFFu, v0, 3);
    float obj = __shfl_sync(0xFFFFFFFFu, v0, 4);

    float c = (lane >= 5u) ? v0 : -3.4e38f;
    int   p = (lane >= 5u) ? (int)lane - 5 : (1 << 30);
    if (v1 > c) { c = v1; p = (int)lane + 27; }
    if (v2 > c) { c = v2; p = (int)lane + 59; }
    #pragma unroll
    for (int off = 16; off; off >>= 1) {
        float oc = __shfl_xor_sync(0xFFFFFFFFu, c, off);
        int   op = __shfl_xor_sync(0xFFFFFFFFu, p, off);
        if (oc > c || (oc == c && op < p)) { c = oc; p = op; }
    }

    float conf  = __fmul_rn(obj, c);
    float score = (conf >= 0.25f) ? obj : NEGF;
    float hw = __fmul_rn(w, 0.5f), hh = __fmul_rn(h, 0.5f);

    if (lane == 0u) {
        g_score[gw] = score;
        if (score != NEGF) atomicAdd(&g_hist1[fkey(score) >> 16], 1u);
        g_rec[gw * 2] = make_float4(__fsub_rn(cx, hw), __fsub_rn(cy, hh),
                                    __fadd_rn(cx, hw), __fadd_rn(cy, hh));
    } else if (lane == 1u) {
        g_rec[gw * 2 + 1] = make_float4(obj, c, (float)p, 0.0f);
    }
}

// ---------------- K2: find top-16-bit boundary bin ----------------
__global__ void k_scan1() {
    __shared__ unsigned suf[1024];
    unsigned t = threadIdx.x;
    unsigned negbin = fkey(NEGF) >> 16;
    unsigned base = t * 64u;
    unsigned raw = 0u;
    for (int b = 0; b < 64; b++) raw += g_hist1[base + b];
    suf[t] = raw;
    __syncthreads();
    for (unsigned off = 1; off < 1024; off <<= 1) {
        unsigned v = (t + off < 1024u) ? suf[t + off] : 0u;
        __syncthreads();
        suf[t] += v;
        __syncthreads();
    }
    unsigned total   = suf[0];
    unsigned negcnt  = NROWS - total;
    unsigned negchk  = negbin >> 6;
    unsigned Sinc = suf[t] + ((negchk >= t) ? negcnt : 0u);
    unsigned csA  = raw + ((t == negchk) ? negcnt : 0u);
    unsigned Sexc = Sinc - csA;
    if (Sexc < KTOP && Sinc >= KTOP) {
        unsigned cum = Sexc;
        for (int b = 63; b >= 0; b--) {
            unsigned bb = base + (unsigned)b;
            unsigned hv = g_hist1[bb] + ((bb == negbin) ? negcnt : 0u);
            cum += hv;
            if (cum >= KTOP) { g_b1 = bb; g_K2 = KTOP - (cum - hv); break; }
        }
    }
}

// ---------------- K3: hist round 2 (low 16 bits, boundary bin only) ----------------
__global__ void k_hist2() {
    unsigned i = blockIdx.x * blockDim.x + threadIdx.x;
    if (i >= NROWS) return;
    unsigned key = fkey(g_score[i]);
    if ((key >> 16) == g_b1) atomicAdd(&g_hist2[key & 0xFFFFu], 1u);
}

// ---------------- K4: exact k-th key value ----------------
__global__ void k_scan2() {
    __shared__ unsigned suf[1024];
    unsigned t = threadIdx.x;
    unsigned K2v = g_K2;
    unsigned b1v = g_b1;
    unsigned base = t * 64u;
    unsigned raw = 0u;
    for (int b = 0; b < 64; b++) raw += g_hist2[base + b];
    suf[t] = raw;
    __syncthreads();
    for (unsigned off = 1; off < 1024; off <<= 1) {
        unsigned v = (t + off < 1024u) ? suf[t + off] : 0u;
        __syncthreads();
        suf[t] += v;
        __syncthreads();
    }
    unsigned Sinc = suf[t];
    unsigned Sexc = Sinc - raw;
    if (Sexc < K2v && Sinc >= K2v) {
        unsigned cum = Sexc;
        for (int b = 63; b >= 0; b--) {
            unsigned bb = base + (unsigned)b;
            unsigned hv = g_hist2[bb];
            cum += hv;
            if (cum >= K2v) {
                g_Vk  = (b1v << 16) | bb;
                g_teq = K2v - (cum - hv);
                break;
            }
        }
    }
}

// ---------------- K5: compact strict-greater + equals ----------------
__global__ void k_compact() {
    unsigned i = blockIdx.x * blockDim.x + threadIdx.x;
    if (i >= NROWS) return;
    unsigned key = fkey(g_score[i]);
    unsigned Vk = g_Vk;
    if (key > Vk) {
        unsigned pnew = atomicAdd(&g_cntA, 1u);
        if (pnew < KTOP) g_A[pnew] = make_uint2(key, i);
    } else if (key == Vk) {
        unsigned pnew = atomicAdd(&g_cntE, 1u);
        if (pnew < ECAP) g_E[pnew] = i;
    }
}

// ---------------- K6: assemble + sort top-K exactly like lax.top_k ----------------
__global__ void k_topk() {
    __shared__ unsigned eidx[ECAP];
    __shared__ unsigned long long prs[KTOP];
    unsigned t = threadIdx.x;
    unsigned cntE = min(g_cntE, (unsigned)ECAP);
    unsigned teq  = g_teq;
    unsigned Vk   = g_Vk;

    for (unsigned x = t; x < ECAP; x += 1024u)
        eidx[x] = (x < cntE) ? g_E[x] : 0xFFFFFFFFu;
    __syncthreads();
    // bitonic sort equals ascending by index
    for (unsigned kk = 2; kk <= ECAP; kk <<= 1)
        for (unsigned j = kk >> 1; j > 0; j >>= 1) {
            for (unsigned x = t; x < ECAP; x += 1024u) {
                unsigned ixj = x ^ j;
                if (ixj > x) {
                    unsigned a = eidx[x], b = eidx[ixj];
                    bool up = ((x & kk) == 0u);
                    if ((a > b) == up) { eidx[x] = b; eidx[ixj] = a; }
                }
            }
            __syncthreads();
        }

    unsigned C1 = KTOP - teq;
    unsigned long long pr;
    if (t < C1) {
        uint2 a = g_A[t];
        pr = ((unsigned long long)a.x << 32) | (unsigned)(~a.y);
    } else {
        unsigned id = eidx[t - C1];
        pr = ((unsigned long long)Vk << 32) | (unsigned)(~id);
    }
    prs[t] = pr;
    __syncthreads();
    // bitonic sort pairs descending by (key, ~idx) -> score desc, idx asc
    for (unsigned kk = 2; kk <= KTOP; kk <<= 1)
        for (unsigned j = kk >> 1; j > 0; j >>= 1) {
            unsigned ixj = t ^ j;
            if (ixj > t) {
                unsigned long long a = prs[t], b = prs[ixj];
                bool up = ((t & kk) == 0u);
                if ((a < b) == up) { prs[t] = b; prs[ixj] = a; }
            }
            __syncthreads();
        }

    pr = prs[t];
    unsigned key = (unsigned)(pr >> 32);
    unsigned idx = ~(unsigned)pr;
    unsigned ub  = (key & 0x80000000u) ? (key ^ 0x80000000u) : ~key;
    float s = __uint_as_float(ub);
    g_valid[t] = (s > -5.0e8f) ? 1 : 0;
    g_boxes[t] = g_rec[(size_t)idx * 2];
    g_info[t]  = g_rec[(size_t)idx * 2 + 1];
}

// ---------------- K7: 1024x1024 IoU suppression bitmask ----------------
__global__ void k_iou() {
    __shared__ float4 sb[KTOP];
    unsigned t = threadIdx.x;
    for (unsigned x = t; x < KTOP; x += 256u) sb[x] = g_boxes[x];
    __syncthreads();
    unsigned w = blockIdx.x * 256u + t;
    unsigned i = w >> 4, blk = w & 15u;
    float4 bi = sb[i];
    float ai = __fmul_rn(__fsub_rn(bi.z, bi.x), __fsub_rn(bi.w, bi.y));
    unsigned long long bits = 0ull;
    unsigned jbase = blk * 64u;
    #pragma unroll 4
    for (int jj = 0; jj < 64; jj++) {
        float4 bj = sb[jbase + jj];
        float aj = __fmul_rn(__fsub_rn(bj.z, bj.x), __fsub_rn(bj.w, bj.y));
        float ltx = fmaxf(bi.x, bj.x), lty = fmaxf(bi.y, bj.y);
        float rbx = fminf(bi.z, bj.z), rby = fminf(bi.w, bj.w);
        float wx = fmaxf(__fsub_rn(rbx, ltx), 0.0f);
        float wy = fmaxf(__fsub_rn(rby, lty), 0.0f);
        float inter = __fmul_rn(wx, wy);
        float uni = __fsub_rn(__fadd_rn(ai, aj), inter);
        float iou = __fdiv_rn(inter, fmaxf(uni, 1e-9f));
        bits |= ((unsigned long long)(iou > 0.65f)) << jj;
    }
    g_M[(size_t)i * 16 + blk] = bits;
}

// ---------------- K8: serial greedy NMS + output ----------------
__global__ void k_nms(float* __restrict__ out, int keepmode) {
    extern __shared__ unsigned long long Ms[];          // KTOP*16 words
    int* keepf = (int*)&Ms[KTOP * 16];                  // KTOP ints
    unsigned t = threadIdx.x;
    for (unsigned x = t; x < KTOP * 16u; x += 1024u) Ms[x] = g_M[x];
    __syncthreads();

    if (t < 32u) {
        unsigned lane = t;
        unsigned long long remv = 0ull, vm = 0ull;
        if (lane < 16u) {
            for (int jj = 0; jj < 64; jj++)
                vm |= ((unsigned long long)(g_valid[lane * 64 + jj] & 1)) << jj;
        }
        for (int i = 0; i < KTOP; i++) {
            unsigned long long mrow = (lane < 16u) ? Ms[(size_t)i * 16 + lane] : 0ull;
            int w_i = i >> 6;
            int pred = 0;
            if ((int)lane == w_i)
                pred = (int)((vm >> (i & 63)) & ~(remv >> (i & 63)) & 1ull);
            unsigned bal = __ballot_sync(0xFFFFFFFFu, pred);
            if (bal) remv |= mrow;
            if (lane == 0u) keepf[i] = (bal != 0u);
        }
    }
    __syncthreads();

    float m = keepf[t] ? 1.0f : 0.0f;
    float4 b = g_boxes[t];
    float4 inf = g_info[t];
    float* o = out + (size_t)t * 7;
    o[0] = __fmul_rn(b.x, m);  o[1] = __fmul_rn(b.y, m);
    o[2] = __fmul_rn(b.z, m);  o[3] = __fmul_rn(b.w, m);
    o[4] = __fmul_rn(inf.x, m); o[5] = __fmul_rn(inf.y, m); o[6] = __fmul_rn(inf.z, m);
    if (keepmode == 0)
        out[KTOP * 7 + t] = m;                              // keep as float 0/1
    else
        ((unsigned char*)(out + KTOP * 7))[t] = (unsigned char)(keepf[t] ? 1 : 0);
}

// ---------------- host ----------------
extern "C" void kernel_launch(void* const* d_in, const int* in_sizes, int n_in,
                              void* d_out, int out_size) {
    const float* pred = (const float*)d_in[0];
    float* out = (float*)d_out;
    int keepmode = 0;                              // default: keep stored as float32 0/1
    if (out_size == KTOP * 7 + KTOP / 4) keepmode = 1;  // keep packed as bool bytes

    k_init<<<256, 256>>>();
    k_score<<<NROWS / 8, 256>>>(pred);
    k_scan1<<<1, 1024>>>();
    k_hist2<<<NROWS / 256, 256>>>();
    k_scan2<<<1, 1024>>>();
    k_compact<<<NROWS / 256, 256>>>();
    k_topk<<<1, 1024>>>();
    k_iou<<<64, 256>>>();

    size_t nms_smem = (size_t)KTOP * 16 * 8 + (size_t)KTOP * 4;
    cudaFuncSetAttribute(k_nms, cudaFuncAttributeMaxDynamicSharedMemorySize,
                         (int)nms_smem);
    k_nms<<<1, 1024, nms_smem>>>(out, keepmode);
}